// round 6
// baseline (speedup 1.0000x reference)
#include <cuda_runtime.h>
#include <cstdint>

// Problem constants (fixed by the dataset)
#define NNODES 50000
#define NFEAT  96
#define NEDGES 800000
#define NCHUNK (NFEAT / 4)   // 24 float4 chunks per node row

// Scratch (allocation-free rule: __device__ globals)
__device__ float g_dinv[NNODES];                         // degree -> rsqrt(degree)
__device__ __align__(16) float g_h1[NNODES * NFEAT];     // intermediate after hop 1
__device__ float g_w [NEDGES];                           // per-edge normalized weight
__device__ int   g_s32[NEDGES];                          // src as int32
__device__ int   g_d32[NEDGES];                          // dst as int32
__device__ int   g_idx_is_i32;                           // 1 if edge_index is int32

// ---------------------------------------------------------------------------
// 0) dtype probe: interpret first K entries as int64; any value outside [0,N)
//    means the buffer is really int32. Single block.
__global__ void k_detect_dtype(const long long* __restrict__ ei64, int e, int n) {
    __shared__ int flag;
    if (threadIdx.x == 0) flag = 0;
    __syncthreads();
    int k = e < 4096 ? e : 4096;
    for (int i = threadIdx.x; i < k; i += blockDim.x) {
        long long v = ei64[i];                 // within first 32KB: safe either way
        if (v < 0 || v >= (long long)n) flag = 1;
    }
    __syncthreads();
    if (threadIdx.x == 0) g_idx_is_i32 = flag;
}

// 1) deg init: self-loop contributes 1 to every node's degree
__global__ void k_init_deg(int n) {
    int i = blockIdx.x * blockDim.x + threadIdx.x;
    if (i < n) g_dinv[i] = 1.0f;
}

// 2) count degree over dst (float atomics; counts < 2^24 so exact)
__global__ void k_count_deg(const void* __restrict__ ei, int e, int n) {
    int i = blockIdx.x * blockDim.x + threadIdx.x;
    if (i >= e) return;
    int d;
    if (g_idx_is_i32) d = ((const int*)ei)[e + i];               // row 1 = dst
    else              d = (int)((const long long*)ei)[e + i];
    if (d >= 0 && d < n) atomicAdd(&g_dinv[d], 1.0f);
}

// 3) deg -> deg^{-1/2}
__global__ void k_rsqrt(int n) {
    int i = blockIdx.x * blockDim.x + threadIdx.x;
    if (i < n) g_dinv[i] = rsqrtf(g_dinv[i]);
}

// 4) fold edges: (any int width) -> int32 indices + precomputed weight
__global__ void k_prep_edges(const void* __restrict__ ei, int e, int n) {
    int i = blockIdx.x * blockDim.x + threadIdx.x;
    if (i >= e) return;
    int s, d;
    if (g_idx_is_i32) {
        const int* p = (const int*)ei;
        s = p[i]; d = p[e + i];
    } else {
        const long long* p = (const long long*)ei;
        s = (int)p[i]; d = (int)p[e + i];
    }
    // clamp defensively (reference guarantees in-range)
    s = (s < 0) ? 0 : (s >= n ? n - 1 : s);
    d = (d < 0) ? 0 : (d >= n ? n - 1 : d);
    g_s32[i] = s;
    g_d32[i] = d;
    g_w[i]   = g_dinv[s] * g_dinv[d];
}

// 5) self-loop term initializes hop output: out[i] = dinv[i]^2 * h[i]
__global__ void k_self_init(const float* __restrict__ h,
                            float* __restrict__ out, int n) {
    int t = blockIdx.x * blockDim.x + threadIdx.x;       // n * NCHUNK threads
    if (t >= n * NCHUNK) return;
    int node  = t / NCHUNK;
    int chunk = t - node * NCHUNK;
    float di = g_dinv[node];
    float w  = di * di;
    const float4 v = reinterpret_cast<const float4*>(h)[node * NCHUNK + chunk];
    float4 o;
    o.x = v.x * w; o.y = v.y * w; o.z = v.z * w; o.w = v.w * w;
    reinterpret_cast<float4*>(out)[node * NCHUNK + chunk] = o;
}

// 6) edge propagation: one thread per (edge, float4 chunk).
//    Gather float4 from src row, scatter 4 scalar atomicAdds (RED) to dst row.
__global__ void k_edge_prop(const float* __restrict__ h,
                            float* __restrict__ out, int e) {
    long long t = (long long)blockIdx.x * blockDim.x + threadIdx.x;
    long long total = (long long)e * NCHUNK;
    if (t >= total) return;
    int edge  = (int)(t / NCHUNK);
    int chunk = (int)(t - (long long)edge * NCHUNK);

    int   s = __ldg(&g_s32[edge]);
    int   d = __ldg(&g_d32[edge]);
    float w = __ldg(&g_w[edge]);

    const float4 v = reinterpret_cast<const float4*>(h)[(size_t)s * NCHUNK + chunk];
    float* p = out + (size_t)d * NFEAT + chunk * 4;
    atomicAdd(p + 0, v.x * w);
    atomicAdd(p + 1, v.y * w);
    atomicAdd(p + 2, v.z * w);
    atomicAdd(p + 3, v.w * w);
}

// ---------------------------------------------------------------------------
extern "C" void kernel_launch(void* const* d_in, const int* in_sizes, int n_in,
                              void* d_out, int out_size) {
    // Resolve input slots by size signature:
    //   x          : NNODES * NFEAT = 4,800,000 elements
    //   edge_index : 2 * NEDGES     = 1,600,000 elements
    int xi = 0, eii = 1;
    if (n_in >= 2 && in_sizes[0] == 2 * NEDGES) { xi = 1; eii = 0; }

    const float* x  = (const float*)d_in[xi];
    const void*  ei = d_in[eii];
    float* out = (float*)d_out;

    const int N = in_sizes[xi] / NFEAT;
    const int E = in_sizes[eii] / 2;

    float* h1;
    cudaGetSymbolAddress((void**)&h1, g_h1);

    const int TB = 256;

    // dtype probe + degree/normalization prep
    k_detect_dtype<<<1, 256>>>((const long long*)ei, E, N);
    k_init_deg  <<<(N + TB - 1) / TB, TB>>>(N);
    k_count_deg <<<(E + TB - 1) / TB, TB>>>(ei, E, N);
    k_rsqrt     <<<(N + TB - 1) / TB, TB>>>(N);
    k_prep_edges<<<(E + TB - 1) / TB, TB>>>(ei, E, N);

    const long long ework = (long long)E * NCHUNK;
    const int eblocks = (int)((ework + TB - 1) / TB);

    // hop 1: x -> h1
    {
        int nt = N * NCHUNK;
        k_self_init<<<(nt + TB - 1) / TB, TB>>>(x, h1, N);
        k_edge_prop<<<eblocks, TB>>>(x, h1, E);
    }
    // hop 2: h1 -> out
    {
        int nt = N * NCHUNK;
        k_self_init<<<(nt + TB - 1) / TB, TB>>>(h1, out, N);
        k_edge_prop<<<eblocks, TB>>>(h1, out, E);
    }
}

// round 12
// speedup vs baseline: 2.5154x; 2.5154x over previous
#include <cuda_runtime.h>
#include <cstdint>

// Problem constants (fixed by the dataset)
#define NNODES 50000
#define NFEAT  96
#define NEDGES 800000
#define NCHUNK (NFEAT / 4)

#define SCAN_B 1024
#define NBLK_SCAN ((NNODES + SCAN_B - 1) / SCAN_B)   // 49

// Scratch (allocation-free rule: __device__ globals)
__device__ float g_dinv[NNODES];
__device__ __align__(16) float g_h1[NNODES * NFEAT];     // intermediate hop-1 output
__device__ int   g_s32[NEDGES];                          // decoded src
__device__ int   g_d32[NEDGES];                          // decoded dst
__device__ int   g_cnt[NNODES];                          // in-edge count per dst
__device__ int   g_row[NNODES + 1];                      // CSR row_ptr
__device__ int   g_cur[NNODES];                          // scatter cursors
__device__ int   g_bsum[NBLK_SCAN];                      // per-block scan totals
__device__ int   g_boff[NBLK_SCAN];                      // scanned block offsets
__device__ int   g_es[NEDGES];                           // CSR: src per slot
__device__ float g_ew[NEDGES];                           // CSR: weight per slot
__device__ int   g_idx_is_i32;

// ---------------------------------------------------------------------------
// 0) dtype probe: any int64-interpreted value outside [0,N) => buffer is int32
__global__ void k_detect_dtype(const long long* __restrict__ ei64, int e, int n) {
    __shared__ int flag;
    if (threadIdx.x == 0) flag = 0;
    __syncthreads();
    int k = e < 4096 ? e : 4096;
    for (int i = threadIdx.x; i < k; i += blockDim.x) {
        long long v = ei64[i];
        if (v < 0 || v >= (long long)n) flag = 1;
    }
    __syncthreads();
    if (threadIdx.x == 0) g_idx_is_i32 = flag;
}

// 1) zero per-dst counters
__global__ void k_zero_cnt(int n) {
    int i = blockIdx.x * blockDim.x + threadIdx.x;
    if (i < n) g_cnt[i] = 0;
}

// 2) decode edges to int32 (+clamp), histogram dst
__global__ void k_prep(const void* __restrict__ ei, int e, int n) {
    int i = blockIdx.x * blockDim.x + threadIdx.x;
    if (i >= e) return;
    int s, d;
    if (g_idx_is_i32) {
        const int* p = (const int*)ei;
        s = p[i]; d = p[e + i];
    } else {
        const long long* p = (const long long*)ei;
        s = (int)p[i]; d = (int)p[e + i];
    }
    s = (s < 0) ? 0 : (s >= n ? n - 1 : s);
    d = (d < 0) ? 0 : (d >= n ? n - 1 : d);
    g_s32[i] = s;
    g_d32[i] = d;
    atomicAdd(&g_cnt[d], 1);
}

// 3) dinv = rsqrt(in_degree + 1)   (self loop adds 1)
__global__ void k_dinv(int n) {
    int i = blockIdx.x * blockDim.x + threadIdx.x;
    if (i < n) g_dinv[i] = rsqrtf((float)(g_cnt[i] + 1));
}

// 4a) per-block inclusive scan of g_cnt -> exclusive into g_row; block total out
__global__ void k_scan_block(int n) {
    __shared__ int sh[SCAN_B];
    int i = blockIdx.x * SCAN_B + threadIdx.x;
    int v = (i < n) ? g_cnt[i] : 0;
    sh[threadIdx.x] = v;
    __syncthreads();
    for (int off = 1; off < SCAN_B; off <<= 1) {
        int t = (threadIdx.x >= off) ? sh[threadIdx.x - off] : 0;
        __syncthreads();
        sh[threadIdx.x] += t;
        __syncthreads();
    }
    if (i < n) g_row[i] = sh[threadIdx.x] - v;       // exclusive
    if (threadIdx.x == SCAN_B - 1) g_bsum[blockIdx.x] = sh[SCAN_B - 1];
}

// 4b) serial exclusive scan of block totals (49 entries)
__global__ void k_scan_top(int nb) {
    if (threadIdx.x == 0) {
        int acc = 0;
        for (int b = 0; b < nb; b++) { g_boff[b] = acc; acc += g_bsum[b]; }
    }
}

// 4c) add block offsets; init cursors; set row[n] = E
__global__ void k_scan_add(int n, int e) {
    int i = blockIdx.x * blockDim.x + threadIdx.x;
    if (i < n) {
        int r = g_row[i] + g_boff[i / SCAN_B];
        g_row[i] = r;
        g_cur[i] = r;
    }
    if (i == 0) g_row[n] = e;
}

// 5) scatter edges into CSR slots (weights precomputed here)
__global__ void k_scatter(int e) {
    int i = blockIdx.x * blockDim.x + threadIdx.x;
    if (i >= e) return;
    int s = g_s32[i];
    int d = g_d32[i];
    int pos = atomicAdd(&g_cur[d], 1);
    g_es[pos] = s;
    g_ew[pos] = g_dinv[s] * g_dinv[d];
}

// 6) pull-mode hop: one block per dst node, 96 threads (one per feature).
//    acc = dinv^2*h[d][f] + sum_e w_e * h[src_e][f];  no atomics.
__global__ void __launch_bounds__(NFEAT) k_hop(const float* __restrict__ h,
                                               float* __restrict__ out) {
    int d = blockIdx.x;
    int f = threadIdx.x;
    int e0 = g_row[d];
    int e1 = g_row[d + 1];
    float di = g_dinv[d];
    float acc = di * di * __ldg(&h[(size_t)d * NFEAT + f]);

    int e = e0;
    // 4-way unroll for memory-level parallelism
    for (; e + 4 <= e1; e += 4) {
        int   s0 = __ldg(&g_es[e]),     s1 = __ldg(&g_es[e + 1]);
        int   s2 = __ldg(&g_es[e + 2]), s3 = __ldg(&g_es[e + 3]);
        float w0 = __ldg(&g_ew[e]),     w1 = __ldg(&g_ew[e + 1]);
        float w2 = __ldg(&g_ew[e + 2]), w3 = __ldg(&g_ew[e + 3]);
        float v0 = __ldg(&h[(size_t)s0 * NFEAT + f]);
        float v1 = __ldg(&h[(size_t)s1 * NFEAT + f]);
        float v2 = __ldg(&h[(size_t)s2 * NFEAT + f]);
        float v3 = __ldg(&h[(size_t)s3 * NFEAT + f]);
        acc += w0 * v0;
        acc += w1 * v1;
        acc += w2 * v2;
        acc += w3 * v3;
    }
    for (; e < e1; ++e)
        acc += __ldg(&g_ew[e]) * __ldg(&h[(size_t)__ldg(&g_es[e]) * NFEAT + f]);

    out[(size_t)d * NFEAT + f] = acc;
}

// ---------------------------------------------------------------------------
extern "C" void kernel_launch(void* const* d_in, const int* in_sizes, int n_in,
                              void* d_out, int out_size) {
    // Resolve input slots by size signature
    int xi = 0, eii = 1;
    if (n_in >= 2 && in_sizes[0] == 2 * NEDGES) { xi = 1; eii = 0; }

    const float* x  = (const float*)d_in[xi];
    const void*  ei = d_in[eii];
    float* out = (float*)d_out;

    const int N = in_sizes[xi] / NFEAT;
    const int E = in_sizes[eii] / 2;

    float* h1;
    cudaGetSymbolAddress((void**)&h1, g_h1);

    const int TB = 256;
    const int nblkN = (N + TB - 1) / TB;
    const int nblkE = (E + TB - 1) / TB;
    const int nbScan = (N + SCAN_B - 1) / SCAN_B;

    // CSR build
    k_detect_dtype<<<1, 256>>>((const long long*)ei, E, N);
    k_zero_cnt   <<<nblkN, TB>>>(N);
    k_prep       <<<nblkE, TB>>>(ei, E, N);
    k_dinv       <<<nblkN, TB>>>(N);
    k_scan_block <<<nbScan, SCAN_B>>>(N);
    k_scan_top   <<<1, 32>>>(nbScan);
    k_scan_add   <<<nblkN, TB>>>(N, E);
    k_scatter    <<<nblkE, TB>>>(E);

    // two pull-mode hops, no atomics
    k_hop<<<N, NFEAT>>>(x,  h1);
    k_hop<<<N, NFEAT>>>(h1, out);
}